// round 4
// baseline (speedup 1.0000x reference)
#include <cuda_runtime.h>

// FraudGNN: 2-layer GCN, N=1M nodes (2 feats), E=32M edges ([2,E] indices).
// Algebra: GCNConv is linear => aggregate in INPUT space.
//   deg[i]   = indeg(i) + 1 (self loop);  dinv = rsqrt(deg)
//   u[i]     = dinv[i] * x[i]
//   agg1[d]  = dinv[d] * (sum_{s->d} u[s] + u[d])
//   h[i]     = relu(agg1[i] @ W1 + b1);  t[i] = h[i] @ W2;  v[i] = dinv[i]*t[i]
//   out[d]   = sigmoid( dinv[d] * (sum_{s->d} v[s] + v[d]) + b2 )
//
// Edge-index dtype is detected at runtime (int32 vs int64): for int64 values
// < 2^31 every odd 32-bit word is 0; for int32 they are real indices.
// All indices are bounds-checked before atomics (err-717 protection).

#define NMAX 1000000

__device__ float  g_deg [NMAX];
__device__ float  g_dinv[NMAX];
__device__ float2 g_u   [NMAX];
__device__ float  g_aggx[NMAX];
__device__ float  g_aggy[NMAX];
__device__ float  g_v   [NMAX];
__device__ int    g_is_i32;

// ---------------------------------------------------------------- zero deg + flag
__global__ void k_zero_deg(int n) {
    int i = blockIdx.x * blockDim.x + threadIdx.x;
    if (i < n) g_deg[i] = 0.0f;
    if (i == 0) g_is_i32 = 0;
}

// ---------------------------------------------------------------- dtype detect
__global__ void k_detect(const unsigned int* __restrict__ w, long long nwords) {
    int i = blockIdx.x * blockDim.x + threadIdx.x;   // samples odd words 1,3,...,8191
    long long p = 2LL * i + 1;
    if (p < nwords && p < 8192) {
        if (w[p] != 0u) g_is_i32 = 1;                // benign race: all writers store 1
    }
}

// index fetch helpers --------------------------------------------------------
// returns 2 indices for edge pair i (edges 2i, 2i+1); has1 = pair complete
__device__ __forceinline__ void load2(const void* base, long long off_elems,
                                      long long i, long long E, int is32,
                                      int& a0, int& a1, bool& has1) {
    long long e0 = 2 * i;
    has1 = (e0 + 1 < E);
    if (is32) {
        const int* p = (const int*)base + off_elems;
        if (has1) { int2 v = ((const int2*)p)[i]; a0 = v.x; a1 = v.y; }
        else      { a0 = p[e0]; a1 = 0; }
    } else {
        const long long* p = (const long long*)base + off_elems;
        if (has1) { longlong2 v = ((const longlong2*)p)[i]; a0 = (int)v.x; a1 = (int)v.y; }
        else      { a0 = (int)p[e0]; a1 = 0; }
    }
}

// ---------------------------------------------------------------- degree (dst only)
__global__ void k_deg(const void* __restrict__ ei, long long E, int n) {
    long long i = (long long)blockIdx.x * blockDim.x + threadIdx.x;
    long long npair = (E + 1) / 2;
    if (i >= npair) return;
    int is32 = g_is_i32;
    int d0, d1; bool has1;
    load2(ei, E, i, E, is32, d0, d1, has1);          // dst = ei + E elements
    if ((unsigned)d0 < (unsigned)n) atomicAdd(&g_deg[d0], 1.0f);
    if (has1 && (unsigned)d1 < (unsigned)n) atomicAdd(&g_deg[d1], 1.0f);
}

// ---------------------------------------------------------------- node pass 1
__global__ void k_node1(const float* __restrict__ x, int n) {
    int i = blockIdx.x * blockDim.x + threadIdx.x;
    if (i >= n) return;
    float deg  = g_deg[i] + 1.0f;            // + self loop
    float dinv = rsqrtf(deg);
    g_dinv[i]  = dinv;
    float2 xv  = ((const float2*)x)[i];
    float ux = xv.x * dinv, uy = xv.y * dinv;
    g_u[i]    = make_float2(ux, uy);
    g_aggx[i] = ux;                          // self-loop contribution
    g_aggy[i] = uy;
}

// ---------------------------------------------------------------- edge pass 1: agg += u[src]
__global__ void k_edge1(const void* __restrict__ ei, long long E, int n) {
    long long i = (long long)blockIdx.x * blockDim.x + threadIdx.x;
    long long npair = (E + 1) / 2;
    if (i >= npair) return;
    int is32 = g_is_i32;
    int s0, s1, d0, d1; bool has1;
    load2(ei, 0, i, E, is32, s0, s1, has1);          // src
    load2(ei, E, i, E, is32, d0, d1, has1);          // dst
    if ((unsigned)s0 < (unsigned)n && (unsigned)d0 < (unsigned)n) {
        float2 u0 = __ldg(&g_u[s0]);
        atomicAdd(&g_aggx[d0], u0.x);
        atomicAdd(&g_aggy[d0], u0.y);
    }
    if (has1 && (unsigned)s1 < (unsigned)n && (unsigned)d1 < (unsigned)n) {
        float2 u1 = __ldg(&g_u[s1]);
        atomicAdd(&g_aggx[d1], u1.x);
        atomicAdd(&g_aggy[d1], u1.y);
    }
}

// ---------------------------------------------------------------- node pass 2: MLP + init out
__global__ void k_node2(const float* __restrict__ W1, const float* __restrict__ b1,
                        const float* __restrict__ W2,
                        float* __restrict__ out, int n) {
    int i = blockIdx.x * blockDim.x + threadIdx.x;
    if (i >= n) return;
    float dinv = g_dinv[i];
    float ax = g_aggx[i] * dinv, ay = g_aggy[i] * dinv;
    float t = 0.0f;
#pragma unroll
    for (int j = 0; j < 8; j++) {
        float y = fmaf(ax, __ldg(&W1[j]), fmaf(ay, __ldg(&W1[8 + j]), __ldg(&b1[j])));
        y = fmaxf(y, 0.0f);                  // relu
        t = fmaf(y, __ldg(&W2[j]), t);       // scalar projection (8 -> 1)
    }
    float v = t * dinv;
    g_v[i] = v;
    out[i] = v;                              // self-loop init of layer-2 accumulator
}

// ---------------------------------------------------------------- edge pass 2: out += v[src]
__global__ void k_edge2(const void* __restrict__ ei, float* __restrict__ out,
                        long long E, int n) {
    long long i = (long long)blockIdx.x * blockDim.x + threadIdx.x;
    long long npair = (E + 1) / 2;
    if (i >= npair) return;
    int is32 = g_is_i32;
    int s0, s1, d0, d1; bool has1;
    load2(ei, 0, i, E, is32, s0, s1, has1);
    load2(ei, E, i, E, is32, d0, d1, has1);
    if ((unsigned)s0 < (unsigned)n && (unsigned)d0 < (unsigned)n)
        atomicAdd(&out[d0], __ldg(&g_v[s0]));
    if (has1 && (unsigned)s1 < (unsigned)n && (unsigned)d1 < (unsigned)n)
        atomicAdd(&out[d1], __ldg(&g_v[s1]));
}

// ---------------------------------------------------------------- final: scale + sigmoid
__global__ void k_final(float* __restrict__ out, const float* __restrict__ b2, int n) {
    int i = blockIdx.x * blockDim.x + threadIdx.x;
    if (i >= n) return;
    float z = fmaf(g_dinv[i], out[i], __ldg(b2));
    out[i] = 1.0f / (1.0f + __expf(-z));
}

// ---------------------------------------------------------------- launch
extern "C" void kernel_launch(void* const* d_in, const int* in_sizes, int n_in,
                              void* d_out, int out_size) {
    const float* x  = (const float*)d_in[0];
    const void*  ei = d_in[1];
    const float* W1 = (const float*)d_in[2];
    const float* b1 = (const float*)d_in[3];
    const float* W2 = (const float*)d_in[4];
    const float* b2 = (const float*)d_in[5];
    float* out = (float*)d_out;

    int       n = in_sizes[0] / 2;            // x is [N, 2]
    long long E = (long long)in_sizes[1] / 2; // edge_index is [2, E] (elem count / 2)

    const int T = 256;
    int nb_node = (n + T - 1) / T;
    long long npair = (E + 1) / 2;
    int nb_edge = (int)((npair + T - 1) / T);

    k_zero_deg<<<nb_node, T>>>(n);
    k_detect  <<<16, T>>>((const unsigned int*)ei, 2 * E); // >= E elems => >= 2E words if i64; use min sample
    k_deg     <<<nb_edge, T>>>(ei, E, n);
    k_node1   <<<nb_node, T>>>(x, n);
    k_edge1   <<<nb_edge, T>>>(ei, E, n);
    k_node2   <<<nb_node, T>>>(W1, b1, W2, out, n);
    k_edge2   <<<nb_edge, T>>>(ei, out, E, n);
    k_final   <<<nb_node, T>>>(out, b2, n);
}

// round 5
// speedup vs baseline: 1.1992x; 1.1992x over previous
#include <cuda_runtime.h>

// FraudGNN: 2-layer GCN, N=1M nodes (2 feats), E=32M edges ([2,E] indices).
// Algebra: GCNConv is linear => aggregate in INPUT space.
//   deg[i]   = indeg(i) + 1 (self loop);  dinv = rsqrt(deg)
//   u[i]     = dinv[i] * x[i]
//   agg1[d]  = dinv[d] * (sum_{s->d} u[s] + u[d])
//   h[i]     = relu(agg1[i] @ W1 + b1);  t[i] = h[i] @ W2;  v[i] = dinv[i]*t[i]
//   out[d]   = sigmoid( dinv[d] * (sum_{s->d} v[s] + v[d]) + b2 )
//
// Indices are int32 on-device (runtime-detected, int64 fallback kept).
// Layer-1 scatter uses vector atomicAdd(float2*) (sm_90+), 4 edges/thread.

#define NMAX 1000000

__device__ float  g_deg [NMAX];
__device__ float  g_dinv[NMAX];
__device__ float2 g_u   [NMAX];
__device__ float2 g_agg [NMAX];
__device__ float  g_v   [NMAX];
__device__ int    g_is_i32;

// ---------------------------------------------------------------- zero deg + dtype detect
__global__ void k_zero_deg(const unsigned int* __restrict__ w, int n) {
    int i = blockIdx.x * blockDim.x + threadIdx.x;
    if (i < n) g_deg[i] = 0.0f;
    if (i == 0) g_is_i32 = 0;
    // int64 indices < 2^31 have zero odd words; int32 odd words are indices.
    if (i < 4096) {
        if (w[2 * i + 1] != 0u) g_is_i32 = 1;   // benign race: all writers store 1
    }
}

// ---------------------------------------------------------------- index fetch (4 per thread)
__device__ __forceinline__ int fetch4(const void* base, long long off_elems,
                                      long long e0, long long E, int is32, int* a) {
    int cnt = (int)((E - e0 < 4) ? (E - e0) : 4);
    if (is32) {
        const int* p = (const int*)base + off_elems;
        if (cnt == 4) {
            int4 v = *(const int4*)(p + e0);
            a[0] = v.x; a[1] = v.y; a[2] = v.z; a[3] = v.w;
        } else {
            for (int k = 0; k < cnt; k++) a[k] = p[e0 + k];
        }
    } else {
        const long long* p = (const long long*)base + off_elems;
        if (cnt == 4) {
            longlong2 v0 = *(const longlong2*)(p + e0);
            longlong2 v1 = *(const longlong2*)(p + e0 + 2);
            a[0] = (int)v0.x; a[1] = (int)v0.y; a[2] = (int)v1.x; a[3] = (int)v1.y;
        } else {
            for (int k = 0; k < cnt; k++) a[k] = (int)p[e0 + k];
        }
    }
    return cnt;
}

// ---------------------------------------------------------------- degree (dst only)
__global__ void k_deg(const void* __restrict__ ei, long long E, int n) {
    long long q = (long long)blockIdx.x * blockDim.x + threadIdx.x;
    long long e0 = 4 * q;
    if (e0 >= E) return;
    int is32 = g_is_i32;
    int d[4];
    int cnt = fetch4(ei, E, e0, E, is32, d);
#pragma unroll
    for (int k = 0; k < 4; k++) {
        if (k < cnt && (unsigned)d[k] < (unsigned)n)
            atomicAdd(&g_deg[d[k]], 1.0f);
    }
}

// ---------------------------------------------------------------- node pass 1
__global__ void k_node1(const float* __restrict__ x, int n) {
    int i = blockIdx.x * blockDim.x + threadIdx.x;
    if (i >= n) return;
    float deg  = g_deg[i] + 1.0f;            // + self loop
    float dinv = rsqrtf(deg);
    g_dinv[i]  = dinv;
    float2 xv  = ((const float2*)x)[i];
    float2 u   = make_float2(xv.x * dinv, xv.y * dinv);
    g_u[i]   = u;
    g_agg[i] = u;                            // self-loop contribution
}

// ---------------------------------------------------------------- edge pass 1: agg += u[src]
__global__ void k_edge1(const void* __restrict__ ei, long long E, int n) {
    long long q = (long long)blockIdx.x * blockDim.x + threadIdx.x;
    long long e0 = 4 * q;
    if (e0 >= E) return;
    int is32 = g_is_i32;
    int s[4], d[4];
    int cnt = fetch4(ei, 0, e0, E, is32, s);
    fetch4(ei, E, e0, E, is32, d);
#pragma unroll
    for (int k = 0; k < 4; k++) {
        if (k < cnt && (unsigned)s[k] < (unsigned)n && (unsigned)d[k] < (unsigned)n) {
            float2 u = __ldg(&g_u[s[k]]);
            atomicAdd(&g_agg[d[k]], u);      // single 64-bit vector RED
        }
    }
}

// ---------------------------------------------------------------- node pass 2: MLP + init out
__global__ void k_node2(const float* __restrict__ W1, const float* __restrict__ b1,
                        const float* __restrict__ W2,
                        float* __restrict__ out, int n) {
    int i = blockIdx.x * blockDim.x + threadIdx.x;
    if (i >= n) return;
    float dinv = g_dinv[i];
    float2 a   = g_agg[i];
    float ax = a.x * dinv, ay = a.y * dinv;  // completed layer-1 aggregation
    float t = 0.0f;
#pragma unroll
    for (int j = 0; j < 8; j++) {
        float y = fmaf(ax, __ldg(&W1[j]), fmaf(ay, __ldg(&W1[8 + j]), __ldg(&b1[j])));
        y = fmaxf(y, 0.0f);                  // relu
        t = fmaf(y, __ldg(&W2[j]), t);       // scalar projection (8 -> 1)
    }
    float v = t * dinv;
    g_v[i] = v;
    out[i] = v;                              // self-loop init of layer-2 accumulator
}

// ---------------------------------------------------------------- edge pass 2: out += v[src]
__global__ void k_edge2(const void* __restrict__ ei, float* __restrict__ out,
                        long long E, int n) {
    long long q = (long long)blockIdx.x * blockDim.x + threadIdx.x;
    long long e0 = 4 * q;
    if (e0 >= E) return;
    int is32 = g_is_i32;
    int s[4], d[4];
    int cnt = fetch4(ei, 0, e0, E, is32, s);
    fetch4(ei, E, e0, E, is32, d);
#pragma unroll
    for (int k = 0; k < 4; k++) {
        if (k < cnt && (unsigned)s[k] < (unsigned)n && (unsigned)d[k] < (unsigned)n)
            atomicAdd(&out[d[k]], __ldg(&g_v[s[k]]));
    }
}

// ---------------------------------------------------------------- final: scale + sigmoid
__global__ void k_final(float* __restrict__ out, const float* __restrict__ b2, int n) {
    int i = blockIdx.x * blockDim.x + threadIdx.x;
    if (i >= n) return;
    float z = fmaf(g_dinv[i], out[i], __ldg(b2));
    out[i] = 1.0f / (1.0f + __expf(-z));
}

// ---------------------------------------------------------------- launch
extern "C" void kernel_launch(void* const* d_in, const int* in_sizes, int n_in,
                              void* d_out, int out_size) {
    const float* x  = (const float*)d_in[0];
    const void*  ei = d_in[1];
    const float* W1 = (const float*)d_in[2];
    const float* b1 = (const float*)d_in[3];
    const float* W2 = (const float*)d_in[4];
    const float* b2 = (const float*)d_in[5];
    float* out = (float*)d_out;

    int       n = in_sizes[0] / 2;            // x is [N, 2]
    long long E = (long long)in_sizes[1] / 2; // edge_index is [2, E]

    const int T = 256;
    int nb_node = (n + T - 1) / T;
    long long nquad = (E + 3) / 4;
    int nb_edge = (int)((nquad + T - 1) / T);

    k_zero_deg<<<nb_node, T>>>((const unsigned int*)ei, n);
    k_deg     <<<nb_edge, T>>>(ei, E, n);
    k_node1   <<<nb_node, T>>>(x, n);
    k_edge1   <<<nb_edge, T>>>(ei, E, n);
    k_node2   <<<nb_node, T>>>(W1, b1, W2, out, n);
    k_edge2   <<<nb_edge, T>>>(ei, out, E, n);
    k_final   <<<nb_node, T>>>(out, b2, n);
}

// round 6
// speedup vs baseline: 1.2062x; 1.0058x over previous
#include <cuda_runtime.h>

// FraudGNN: 2-layer GCN, N=1M nodes (2 feats), E=32M edges ([2,E] int32 on-device).
// Algebra: GCNConv is linear => aggregate in INPUT space.
//   deg[i]   = indeg(i) + 1 (self loop);  dinv = rsqrt(deg)
//   u[i]     = dinv[i] * x[i]
//   agg1[d]  = dinv[d] * (sum_{s->d} u[s] + u[d])
//   h[i]     = relu(agg1[i] @ W1 + b1);  t[i] = h[i] @ W2;  v[i] = dinv[i]*t[i]
//   out[d]   = sigmoid( dinv[d] * (sum_{s->d} v[s] + v[d]) + b2 )
//
// LTS-bound: 5 L2 ops/edge floor (deg RED + gather/RED per layer).
// 8 edges/thread, __ldcs on index streams, float2 vector REDs in layer 1.

#define NMAX 1000000

__device__ float  g_deg [NMAX];
__device__ float  g_dinv[NMAX];
__device__ float2 g_u   [NMAX];
__device__ float2 g_agg [NMAX];
__device__ float  g_v   [NMAX];
__device__ int    g_is_i32;

// ---------------------------------------------------------------- zero deg + dtype detect
__global__ void k_zero_deg(const unsigned int* __restrict__ w, int n) {
    int i = blockIdx.x * blockDim.x + threadIdx.x;
    int i4 = 4 * i;
    if (i4 + 3 < n) {
        ((float4*)g_deg)[i] = make_float4(0.f, 0.f, 0.f, 0.f);
    } else {
        for (int k = i4; k < n; k++) g_deg[k] = 0.0f;
    }
    if (i == 0) g_is_i32 = 0;
    // int64 indices < 2^31 have zero odd 32-bit words; int32 odd words are indices.
    if (i < 4096) {
        if (w[2 * i + 1] != 0u) g_is_i32 = 1;   // benign race: all writers store 1
    }
}

// ---------------------------------------------------------------- index fetch: 8 indices
__device__ __forceinline__ void fetch8_i32(const int* __restrict__ p, long long e0, int* a) {
    int4 v0 = __ldcs((const int4*)(p + e0));
    int4 v1 = __ldcs((const int4*)(p + e0) + 1);
    a[0] = v0.x; a[1] = v0.y; a[2] = v0.z; a[3] = v0.w;
    a[4] = v1.x; a[5] = v1.y; a[6] = v1.z; a[7] = v1.w;
}

__device__ __forceinline__ int fetch8_any(const void* base, long long off_elems,
                                          long long e0, long long E, int is32, int* a) {
    long long rem = E - e0;
    int cnt = (int)(rem < 8 ? rem : 8);
    if (is32) {
        const int* p = (const int*)base + off_elems;
        if (cnt == 8) { fetch8_i32(p, e0, a); }
        else { for (int k = 0; k < cnt; k++) a[k] = p[e0 + k]; }
    } else {
        const long long* p = (const long long*)base + off_elems;
        for (int k = 0; k < cnt; k++) a[k] = (int)p[e0 + k];
    }
    return cnt;
}

// ---------------------------------------------------------------- degree (dst only)
__global__ void k_deg(const void* __restrict__ ei, long long E, int n) {
    long long q = (long long)blockIdx.x * blockDim.x + threadIdx.x;
    long long e0 = 8 * q;
    if (e0 >= E) return;
    int d[8];
    int cnt = fetch8_any(ei, E, e0, E, g_is_i32, d);
    if (cnt == 8) {
#pragma unroll
        for (int k = 0; k < 8; k++)
            if ((unsigned)d[k] < (unsigned)n) atomicAdd(&g_deg[d[k]], 1.0f);
    } else {
        for (int k = 0; k < cnt; k++)
            if ((unsigned)d[k] < (unsigned)n) atomicAdd(&g_deg[d[k]], 1.0f);
    }
}

// ---------------------------------------------------------------- node pass 1 (2 nodes/thread)
__global__ void k_node1(const float* __restrict__ x, int n) {
    int i = blockIdx.x * blockDim.x + threadIdx.x;
    int i0 = 2 * i;
    if (i0 >= n) return;
    if (i0 + 1 < n) {
        float2 dg = ((const float2*)g_deg)[i];
        float4 xv = ((const float4*)x)[i];
        float di0 = rsqrtf(dg.x + 1.0f);
        float di1 = rsqrtf(dg.y + 1.0f);
        ((float2*)g_dinv)[i] = make_float2(di0, di1);
        float4 u = make_float4(xv.x * di0, xv.y * di0, xv.z * di1, xv.w * di1);
        ((float4*)g_u)[i]   = u;
        ((float4*)g_agg)[i] = u;             // self-loop contribution
    } else {
        float dinv = rsqrtf(g_deg[i0] + 1.0f);
        g_dinv[i0] = dinv;
        float2 xv = ((const float2*)x)[i0];
        float2 u  = make_float2(xv.x * dinv, xv.y * dinv);
        g_u[i0] = u; g_agg[i0] = u;
    }
}

// ---------------------------------------------------------------- edge pass 1: agg += u[src]
__global__ void k_edge1(const void* __restrict__ ei, long long E, int n) {
    long long q = (long long)blockIdx.x * blockDim.x + threadIdx.x;
    long long e0 = 8 * q;
    if (e0 >= E) return;
    int is32 = g_is_i32;
    int s[8], d[8];
    int cnt = fetch8_any(ei, 0, e0, E, is32, s);
    fetch8_any(ei, E, e0, E, is32, d);
    if (cnt == 8) {
        float2 u[8];
#pragma unroll
        for (int k = 0; k < 8; k++) {
            bool ok = (unsigned)s[k] < (unsigned)n;
            u[k] = ok ? __ldg(&g_u[s[k]]) : make_float2(0.f, 0.f);
        }
#pragma unroll
        for (int k = 0; k < 8; k++) {
            if ((unsigned)s[k] < (unsigned)n && (unsigned)d[k] < (unsigned)n)
                atomicAdd(&g_agg[d[k]], u[k]);   // 64-bit vector RED
        }
    } else {
        for (int k = 0; k < cnt; k++) {
            if ((unsigned)s[k] < (unsigned)n && (unsigned)d[k] < (unsigned)n)
                atomicAdd(&g_agg[d[k]], __ldg(&g_u[s[k]]));
        }
    }
}

// ---------------------------------------------------------------- node pass 2: MLP + init out
__global__ void k_node2(const float* __restrict__ W1, const float* __restrict__ b1,
                        const float* __restrict__ W2,
                        float* __restrict__ out, int n) {
    int i = blockIdx.x * blockDim.x + threadIdx.x;
    int i0 = 2 * i;
    if (i0 >= n) return;
    int lim = (i0 + 1 < n) ? 2 : 1;
    float2 vv;
#pragma unroll
    for (int m = 0; m < 2; m++) {
        if (m >= lim) break;
        int idx = i0 + m;
        float dinv = g_dinv[idx];
        float2 a   = g_agg[idx];
        float ax = a.x * dinv, ay = a.y * dinv;
        float t = 0.0f;
#pragma unroll
        for (int j = 0; j < 8; j++) {
            float y = fmaf(ax, __ldg(&W1[j]), fmaf(ay, __ldg(&W1[8 + j]), __ldg(&b1[j])));
            y = fmaxf(y, 0.0f);
            t = fmaf(y, __ldg(&W2[j]), t);
        }
        float v = t * dinv;
        (m == 0 ? vv.x : vv.y) = v;
    }
    if (lim == 2) {
        ((float2*)g_v)[i] = vv;
        ((float2*)out)[i] = vv;              // self-loop init of layer-2 accumulator
    } else {
        g_v[i0] = vv.x;
        out[i0] = vv.x;
    }
}

// ---------------------------------------------------------------- edge pass 2: out += v[src]
__global__ void k_edge2(const void* __restrict__ ei, float* __restrict__ out,
                        long long E, int n) {
    long long q = (long long)blockIdx.x * blockDim.x + threadIdx.x;
    long long e0 = 8 * q;
    if (e0 >= E) return;
    int is32 = g_is_i32;
    int s[8], d[8];
    int cnt = fetch8_any(ei, 0, e0, E, is32, s);
    fetch8_any(ei, E, e0, E, is32, d);
    if (cnt == 8) {
        float v[8];
#pragma unroll
        for (int k = 0; k < 8; k++) {
            bool ok = (unsigned)s[k] < (unsigned)n;
            v[k] = ok ? __ldg(&g_v[s[k]]) : 0.0f;
        }
#pragma unroll
        for (int k = 0; k < 8; k++) {
            if ((unsigned)s[k] < (unsigned)n && (unsigned)d[k] < (unsigned)n)
                atomicAdd(&out[d[k]], v[k]);
        }
    } else {
        for (int k = 0; k < cnt; k++) {
            if ((unsigned)s[k] < (unsigned)n && (unsigned)d[k] < (unsigned)n)
                atomicAdd(&out[d[k]], __ldg(&g_v[s[k]]));
        }
    }
}

// ---------------------------------------------------------------- final: scale + sigmoid
__global__ void k_final(float* __restrict__ out, const float* __restrict__ b2, int n) {
    int i = blockIdx.x * blockDim.x + threadIdx.x;
    int i0 = 2 * i;
    if (i0 >= n) return;
    float bb = __ldg(b2);
    if (i0 + 1 < n) {
        float2 o  = ((const float2*)out)[i];
        float2 di = ((const float2*)g_dinv)[i];
        float z0 = fmaf(di.x, o.x, bb);
        float z1 = fmaf(di.y, o.y, bb);
        ((float2*)out)[i] = make_float2(1.0f / (1.0f + __expf(-z0)),
                                        1.0f / (1.0f + __expf(-z1)));
    } else {
        float z = fmaf(g_dinv[i0], out[i0], bb);
        out[i0] = 1.0f / (1.0f + __expf(-z));
    }
}

// ---------------------------------------------------------------- launch
extern "C" void kernel_launch(void* const* d_in, const int* in_sizes, int n_in,
                              void* d_out, int out_size) {
    const float* x  = (const float*)d_in[0];
    const void*  ei = d_in[1];
    const float* W1 = (const float*)d_in[2];
    const float* b1 = (const float*)d_in[3];
    const float* W2 = (const float*)d_in[4];
    const float* b2 = (const float*)d_in[5];
    float* out = (float*)d_out;

    int       n = in_sizes[0] / 2;            // x is [N, 2]
    long long E = (long long)in_sizes[1] / 2; // edge_index is [2, E]

    const int T = 256;
    int nb_zero  = ((n + 3) / 4 + T - 1) / T;
    int nb_half  = ((n + 1) / 2 + T - 1) / T;
    long long noct = (E + 7) / 8;
    int nb_edge  = (int)((noct + T - 1) / T);

    k_zero_deg<<<nb_zero, T>>>((const unsigned int*)ei, n);
    k_deg     <<<nb_edge, T>>>(ei, E, n);
    k_node1   <<<nb_half, T>>>(x, n);
    k_edge1   <<<nb_edge, T>>>(ei, E, n);
    k_node2   <<<nb_half, T>>>(W1, b1, W2, out, n);
    k_edge2   <<<nb_edge, T>>>(ei, out, E, n);
    k_final   <<<nb_half, T>>>(out, b2, n);
}